// round 14
// baseline (speedup 1.0000x reference)
#include <cuda_runtime.h>
#include <cuda_bf16.h>

#define D 256
#define NS 16
#define B_ROWS 131072
#define GRID_DOTS 296
#define TOTW_DOTS (GRID_DOTS * 8)
#define GRID_ACC 148
#define NSTREAM_ACC (GRID_ACC * 4)   // 592 row streams (2 warps share a stream, slot halves)
#define LN_EPS 1e-5f
#define ATT_EPS 1e-8f
#define SCALE 0.0625f

typedef unsigned long long ull;

// ---------------- device scratch (static; no runtime allocation) ----------------
__device__ float g_xln[(size_t)B_ROWS * D];   // LN(x), materialized once
__device__ float g_WkT[D * D];                // Wk transposed
__device__ float g_slots[NS * D];
__device__ float g_qk[NS * D];
__device__ float g_cn[NS];
__device__ float g_attn[(size_t)B_ROWS * NS];
__device__ float g_partU[GRID_ACC * NS * D];
__device__ float g_partS[GRID_ACC * NS];
__device__ float g_updates[NS * D];
__device__ float g_gx[NS * 3 * D];
__device__ float g_gh[NS * 3 * D];
__device__ float g_hnew[NS * D];
__device__ float g_hd[NS * D];

// ---------------- helpers ----------------
__device__ __forceinline__ float warp_sum(float v) {
    v += __shfl_xor_sync(0xffffffffu, v, 16);
    v += __shfl_xor_sync(0xffffffffu, v, 8);
    v += __shfl_xor_sync(0xffffffffu, v, 4);
    v += __shfl_xor_sync(0xffffffffu, v, 2);
    v += __shfl_xor_sync(0xffffffffu, v, 1);
    return v;
}

// blockDim.x == 256
__device__ __forceinline__ float block_sum256(float v, float* red) {
    const int lane = threadIdx.x & 31;
    const int w = threadIdx.x >> 5;
    v = warp_sum(v);
    if (lane == 0) red[w] = v;
    __syncthreads();
    if (w == 0) {
        float x = (lane < 8) ? red[lane] : 0.0f;
        x += __shfl_xor_sync(0xffffffffu, x, 4);
        x += __shfl_xor_sync(0xffffffffu, x, 2);
        x += __shfl_xor_sync(0xffffffffu, x, 1);
        if (lane == 0) red[0] = x;
    }
    __syncthreads();
    float r = red[0];
    __syncthreads();
    return r;
}

// blockDim.x == 1024 (threads without data pass 0)
__device__ __forceinline__ float block_sum1024(float v, float* red) {
    const int lane = threadIdx.x & 31;
    const int w = threadIdx.x >> 5;
    v = warp_sum(v);
    if (lane == 0) red[w] = v;
    __syncthreads();
    if (w == 0) {
        float x = red[lane];
        x = warp_sum(x);
        if (lane == 0) red[0] = x;
    }
    __syncthreads();
    float r = red[0];
    __syncthreads();
    return r;
}

__device__ __forceinline__ float dot4(float4 a, float4 b) {
    return a.x * b.x + a.y * b.y + a.z * b.z + a.w * b.w;
}

__device__ __forceinline__ ull pack2(float lo, float hi) {
    ull r;
    asm("mov.b64 %0, {%1, %2};" : "=l"(r) : "f"(lo), "f"(hi));
    return r;
}
__device__ __forceinline__ void unpack2(ull v, float& lo, float& hi) {
    asm("mov.b64 {%0, %1}, %2;" : "=f"(lo), "=f"(hi) : "l"(v));
}
__device__ __forceinline__ void fma2(ull& d, ull a, ull b) {
    asm("fma.rn.f32x2 %0, %1, %2, %0;" : "+l"(d) : "l"(a), "l"(b));
}
__device__ __forceinline__ ull add2(ull a, ull b) {
    ull r;
    asm("add.rn.f32x2 %0, %1, %2;" : "=l"(r) : "l"(a), "l"(b));
    return r;
}
__device__ __forceinline__ ull shfl_xor_u64(ull v, int m) {
    unsigned lo = (unsigned)v, hi = (unsigned)(v >> 32);
    lo = __shfl_xor_sync(0xffffffffu, lo, m);
    hi = __shfl_xor_sync(0xffffffffu, hi, m);
    return ((ull)hi << 32) | lo;
}

__device__ __forceinline__ float sigmoidf_(float x) { return 1.0f / (1.0f + expf(-x)); }

// quad-split dot: thread (j = t>>2, kq = t&3) dots W[j, kq*64 .. +63] with in_s;
// quad-reduced result valid in all 4 lanes of the quad.
__device__ __forceinline__ float fc_dot(const float* __restrict__ W, const float* in_s,
                                        int j, int kq) {
    const float4* w4 = reinterpret_cast<const float4*>(W + (size_t)j * D + kq * 64);
    const float4* s4 = reinterpret_cast<const float4*>(in_s + kq * 64);
    float a0 = 0.0f, a1 = 0.0f, a2 = 0.0f, a3 = 0.0f;
#pragma unroll
    for (int i = 0; i < 16; i += 4) {
        a0 += dot4(w4[i], s4[i]);
        a1 += dot4(w4[i + 1], s4[i + 1]);
        a2 += dot4(w4[i + 2], s4[i + 2]);
        a3 += dot4(w4[i + 3], s4[i + 3]);
    }
    float v = (a0 + a1) + (a2 + a3);
    v += __shfl_xor_sync(0xffffffffu, v, 1);
    v += __shfl_xor_sync(0xffffffffu, v, 2);
    return v;
}

// LN(src[0..255]) -> dst, for 1024-thread blocks (t<256 active); all threads call.
__device__ __forceinline__ void ln256_1024(const float* src, float* dst,
                                           const float* __restrict__ g,
                                           const float* __restrict__ be, float* red) {
    const int t = threadIdx.x;
    const float sv = (t < D) ? src[t] : 0.0f;
    const float m = block_sum1024(sv, red) * (1.0f / (float)D);
    const float dv = sv - m;
    const float var = block_sum1024((t < D) ? dv * dv : 0.0f, red) * (1.0f / (float)D);
    const float rstd = rsqrtf(var + LN_EPS);
    if (t < D) dst[t] = dv * rstd * g[t] + be[t];
    __syncthreads();
}

// q = Wq@s + bq ; qk = SCALE * q @ WkT ; cn = SCALE * q.bk   (1024-thread block, slot n)
__device__ __forceinline__ void q_qk_1024(int n, const float* s_s, float* q_s,
                                          const float* __restrict__ Wq, const float* __restrict__ bq,
                                          const float* __restrict__ bk, float* red) {
    const int t = threadIdx.x;
    const int j = t >> 2, kq = t & 3;
    const float qv = fc_dot(Wq, s_s, j, kq);
    if (kq == 0) q_s[j] = qv + bq[j];
    __syncthreads();
    const float kv = fc_dot(g_WkT, q_s, j, kq);
    if (kq == 0) g_qk[n * D + j] = kv * SCALE;
    const float p = block_sum1024((t < D) ? q_s[t] * bk[t] : 0.0f, red);
    if (t == 0) g_cn[n] = p * SCALE;
}

// ---------------- K: materialize LN(x) once ----------------
__global__ void __launch_bounds__(256)
k_lnx(const float* __restrict__ x,
      const float* __restrict__ gin, const float* __restrict__ bin) {
    const int lane = threadIdx.x & 31;
    const int warp = threadIdx.x >> 5;
    const float4* gin4 = reinterpret_cast<const float4*>(gin);
    const float4* bin4 = reinterpret_cast<const float4*>(bin);
    const float4 gv0 = gin4[lane], gv1 = gin4[lane + 32];
    const float4 bb0 = bin4[lane], bb1 = bin4[lane + 32];

    const float4* x4 = reinterpret_cast<const float4*>(x);
    float4* o4 = reinterpret_cast<float4*>(g_xln);
    const int gw = blockIdx.x * 8 + warp;

    for (int r = gw; r < B_ROWS; r += 1024 * 8) {
        const float4 v0 = x4[(size_t)r * 64 + lane];
        const float4 v1 = x4[(size_t)r * 64 + 32 + lane];
        float sm = v0.x + v0.y + v0.z + v0.w + v1.x + v1.y + v1.z + v1.w;
        float sq = v0.x * v0.x + v0.y * v0.y + v0.z * v0.z + v0.w * v0.w
                 + v1.x * v1.x + v1.y * v1.y + v1.z * v1.z + v1.w * v1.w;
        sm = warp_sum(sm);
        sq = warp_sum(sq);
        const float mean = sm * (1.0f / 256.0f);
        const float var = fmaxf(sq * (1.0f / 256.0f) - mean * mean, 0.0f);
        const float rstd = rsqrtf(var + LN_EPS);
        float4 w0, w1;
        w0.x = (v0.x - mean) * rstd * gv0.x + bb0.x;
        w0.y = (v0.y - mean) * rstd * gv0.y + bb0.y;
        w0.z = (v0.z - mean) * rstd * gv0.z + bb0.z;
        w0.w = (v0.w - mean) * rstd * gv0.w + bb0.w;
        w1.x = (v1.x - mean) * rstd * gv1.x + bb1.x;
        w1.y = (v1.y - mean) * rstd * gv1.y + bb1.y;
        w1.z = (v1.z - mean) * rstd * gv1.z + bb1.z;
        w1.w = (v1.w - mean) * rstd * gv1.w + bb1.w;
        o4[(size_t)r * 64 + lane] = w0;
        o4[(size_t)r * 64 + 32 + lane] = w1;
    }
}

// ---------------- K: transpose Wk (once) ----------------
__global__ void k_wkT(const float* __restrict__ Wk) {
    __shared__ float tile[32][33];
    const int tx = threadIdx.x, ty = threadIdx.y;
    const int xi = blockIdx.x * 32 + tx;
#pragma unroll
    for (int r = 0; r < 32; r += 8)
        tile[ty + r][tx] = Wk[(size_t)(blockIdx.y * 32 + ty + r) * D + xi];
    __syncthreads();
    const int xo = blockIdx.y * 32 + tx;
#pragma unroll
    for (int r = 0; r < 32; r += 8)
        g_WkT[(size_t)(blockIdx.x * 32 + ty + r) * D + xo] = tile[tx][ty + r];
}

// ---------------- K: slots init + LN + q + qk (grid=NS, block=1024) ----------------
__global__ void __launch_bounds__(1024)
k_init(const float* __restrict__ noise, const float* __restrict__ mu,
       const float* __restrict__ sigma,
       const float* __restrict__ Wq, const float* __restrict__ bq,
       const float* __restrict__ bk,
       const float* __restrict__ gs, const float* __restrict__ bes) {
    __shared__ __align__(16) float h_s[D];
    __shared__ __align__(16) float s_s[D];
    __shared__ __align__(16) float q_s[D];
    __shared__ float red[32];
    const int n = blockIdx.x, t = threadIdx.x;

    if (t < D) {
        const float sv = mu[t] + sigma[t] * noise[n * D + t];
        g_slots[n * D + t] = sv;
        h_s[t] = sv;
    }
    __syncthreads();
    ln256_1024(h_s, s_s, gs, bes, red);
    q_qk_1024(n, s_s, q_s, Wq, bq, bk, red);
}

// ---------------- K_dots: 2 rows per qk pass (packed), softmax -> attn ----------------
__global__ void __launch_bounds__(256, 2)
k_dots() {
    __shared__ __align__(16) float qk_s[NS * D];
    __shared__ float cn_s[NS];

    const int tid = threadIdx.x;
    const int lane = tid & 31;
    const int warp = tid >> 5;
    const int sigma = __brev((unsigned)(lane & 15)) >> 28;  // bitrev4

    for (int i = tid; i < NS * D; i += 256) qk_s[i] = g_qk[i];
    if (tid < NS) cn_s[tid] = g_cn[tid];
    __syncthreads();
    const float cn_r = cn_s[sigma];

    const float4* x4 = reinterpret_cast<const float4*>(g_xln);
    const float4* qk4 = reinterpret_cast<const float4*>(qk_s);

    for (int r0 = (blockIdx.x * 8 + warp) * 2; r0 < B_ROWS; r0 += 2 * TOTW_DOTS) {
        // anti-hoist: keep the loop-invariant qk_s LDS loads INSIDE the loop so
        // ptxas does not promote 2KB of qk into registers (cap+spill failure mode)
        asm volatile("" ::: "memory");

        // load rows r0 and r0+1 (r0 even, so r0+1 < B_ROWS always)
        const float4 a0 = x4[(size_t)r0 * 64 + lane];
        const float4 a1 = x4[(size_t)r0 * 64 + 32 + lane];
        const float4 b0 = x4[(size_t)(r0 + 1) * 64 + lane];
        const float4 b1 = x4[(size_t)(r0 + 1) * 64 + 32 + lane];

        const ull xa0 = pack2(a0.x, a0.y), xa1 = pack2(a0.z, a0.w);
        const ull xa2 = pack2(a1.x, a1.y), xa3 = pack2(a1.z, a1.w);
        const ull xb0 = pack2(b0.x, b0.y), xb1 = pack2(b0.z, b0.w);
        const ull xb2 = pack2(b1.x, b1.y), xb3 = pack2(b1.z, b1.w);

        // ---- 16 dots for BOTH rows with ONE qk read ----
        ull D2[NS];  // (dA, dB) packed per slot
#pragma unroll
        for (int n = 0; n < NS; n++) {
            const float4 qa = qk4[n * 64 + lane];
            const float4 qb = qk4[n * 64 + 32 + lane];
            const ull q0 = pack2(qa.x, qa.y), q1 = pack2(qa.z, qa.w);
            const ull q2 = pack2(qb.x, qb.y), q3 = pack2(qb.z, qb.w);
            ull accA = 0ull, accB = 0ull;
            fma2(accA, q0, xa0); fma2(accB, q0, xb0);
            fma2(accA, q1, xa1); fma2(accB, q1, xb1);
            fma2(accA, q2, xa2); fma2(accB, q2, xb2);
            fma2(accA, q3, xa3); fma2(accB, q3, xb3);
            float lA, hA, lB, hB;
            unpack2(accA, lA, hA);
            unpack2(accB, lB, hB);
            D2[n] = pack2(lA + hA, lB + hB);
        }

        // ---- packed halving butterfly: lane l ends with slot bitrev4(l&15), both rows ----
#pragma unroll
        for (int i = 0; i < 8; i++) {
            const ull sent = (lane & 1) ? D2[i] : D2[i + 8];
            const ull recv = shfl_xor_u64(sent, 1);
            D2[i] = add2((lane & 1) ? D2[i + 8] : D2[i], recv);
        }
#pragma unroll
        for (int i = 0; i < 4; i++) {
            const ull sent = (lane & 2) ? D2[i] : D2[i + 4];
            const ull recv = shfl_xor_u64(sent, 2);
            D2[i] = add2((lane & 2) ? D2[i + 4] : D2[i], recv);
        }
#pragma unroll
        for (int i = 0; i < 2; i++) {
            const ull sent = (lane & 4) ? D2[i] : D2[i + 2];
            const ull recv = shfl_xor_u64(sent, 4);
            D2[i] = add2((lane & 4) ? D2[i + 2] : D2[i], recv);
        }
        {
            const ull sent = (lane & 8) ? D2[0] : D2[1];
            const ull recv = shfl_xor_u64(sent, 8);
            D2[0] = add2((lane & 8) ? D2[1] : D2[0], recv);
        }
        D2[0] = add2(D2[0], shfl_xor_u64(D2[0], 16));

        float ddA, ddB;
        unpack2(D2[0], ddA, ddB);
        ddA += cn_r;
        ddB += cn_r;

        // ---- softmax across the 16 slots, both rows ----
        float mA = ddA, mB = ddB;
#pragma unroll
        for (int ofs = 1; ofs < 16; ofs <<= 1) {
            mA = fmaxf(mA, __shfl_xor_sync(0xffffffffu, mA, ofs));
            mB = fmaxf(mB, __shfl_xor_sync(0xffffffffu, mB, ofs));
        }
        const float eA = __expf(ddA - mA);
        const float eB = __expf(ddB - mB);
        float sA = eA, sB = eB;
#pragma unroll
        for (int ofs = 1; ofs < 16; ofs <<= 1) {
            sA += __shfl_xor_sync(0xffffffffu, sA, ofs);
            sB += __shfl_xor_sync(0xffffffffu, sB, ofs);
        }
        const float aA = __fdividef(eA, sA) + ATT_EPS;
        const float aB = __fdividef(eB, sB) + ATT_EPS;

        if (lane < 16) {
            g_attn[(size_t)r0 * NS + sigma] = aA;
            g_attn[(size_t)(r0 + 1) * NS + sigma] = aB;
        }
    }
}

// ---------------- K_accum: slot-split (2 warps share a row stream), 2-row unroll, occ 2 ----
__global__ void __launch_bounds__(256, 2)
k_accum() {
    __shared__ __align__(16) float ublk[NS * D];
    __shared__ float sblk[4][NS];

    const int tid = threadIdx.x;
    const int lane = tid & 31;
    const int warp = tid >> 5;
    const int h = warp & 1;          // slot half: slots h*8 .. h*8+7
    const int stream = warp >> 1;    // row stream within block (0..3)
    const int nbase = h * 8;

    ull u2[8][4];
#pragma unroll
    for (int n = 0; n < 8; n++)
#pragma unroll
        for (int p = 0; p < 4; p++) u2[n][p] = 0ull;
    float s_acc[8];
#pragma unroll
    for (int n = 0; n < 8; n++) s_acc[n] = 0.0f;

    const float4* x4 = reinterpret_cast<const float4*>(g_xln);
    const float4* ag4 = reinterpret_cast<const float4*>(g_attn);

    for (int r0 = (blockIdx.x * 4 + stream) * 2; r0 < B_ROWS; r0 += 2 * NSTREAM_ACC) {
        // rows r0, r0+1 (r0 even -> r0+1 valid); 8 independent loads
        const float4 a0 = x4[(size_t)r0 * 64 + lane];
        const float4 a1 = x4[(size_t)r0 * 64 + 32 + lane];
        const float4 b0 = x4[(size_t)(r0 + 1) * 64 + lane];
        const float4 b1 = x4[(size_t)(r0 + 1) * 64 + 32 + lane];
        // attn: only this warp's 8 slots (2 float4 per row)
        const float4 afA = ag4[(size_t)r0 * 4 + h * 2];
        const float4 afA2 = ag4[(size_t)r0 * 4 + h * 2 + 1];
        const float4 afB = ag4[(size_t)(r0 + 1) * 4 + h * 2];
        const float4 afB2 = ag4[(size_t)(r0 + 1) * 4 + h * 2 + 1];

        const ull xa0 = pack2(a0.x, a0.y), xa1 = pack2(a0.z, a0.w);
        const ull xa2 = pack2(a1.x, a1.y), xa3 = pack2(a1.z, a1.w);
        const ull xb0 = pack2(b0.x, b0.y), xb1 = pack2(b0.z, b0.w);
        const ull xb2 = pack2(b1.x, b1.y), xb3 = pack2(b1.z, b1.w);

        const float av[8] = {afA.x, afA.y, afA.z, afA.w, afA2.x, afA2.y, afA2.z, afA2.w};
        const float bv[8] = {afB.x, afB.y, afB.z, afB.w, afB2.x, afB2.y, afB2.z, afB2.w};
#pragma unroll
        for (int n = 0; n < 8; n++) {
            s_acc[n] += av[n] + bv[n];
            const ull a2 = pack2(av[n], av[n]);
            fma2(u2[n][0], a2, xa0);
            fma2(u2[n][1], a2, xa1);
            fma2(u2[n][2], a2, xa2);
            fma2(u2[n][3], a2, xa3);
            const ull b2v = pack2(bv[n], bv[n]);
            fma2(u2[n][0], b2v, xb0);
            fma2(u2[n][1], b2v, xb1);
            fma2(u2[n][2], b2v, xb2);
            fma2(u2[n][3], b2v, xb3);
        }
    }

    // stage per-warp partials: streams serialize; the two slot-halves of a stream
    // write disjoint slot rows concurrently.
    for (int p = 0; p < 4; p++) {
        if (stream == p) {
#pragma unroll
            for (int n = 0; n < 8; n++) {
                const int nn = nbase + n;
#pragma unroll
                for (int q = 0; q < 4; q++) {
                    float lo, hi;
                    unpack2(u2[n][q], lo, hi);
                    const int c = (q < 2) ? (lane * 4 + 2 * q) : (128 + lane * 4 + 2 * (q - 2));
                    if (p == 0) {
                        ublk[nn * D + c] = lo;
                        ublk[nn * D + c + 1] = hi;
                    } else {
                        ublk[nn * D + c] += lo;
                        ublk[nn * D + c + 1] += hi;
                    }
                }
            }
            if (lane == 0) {
#pragma unroll
                for (int n = 0; n < 8; n++) sblk[p][nbase + n] = s_acc[n];
            }
        }
        __syncthreads();
    }

    for (int i = tid; i < NS * D; i += 256)
        g_partU[(size_t)blockIdx.x * (NS * D) + i] = ublk[i];
    if (tid < NS) {
        float t = 0.0f;
#pragma unroll
        for (int p = 0; p < 4; p++) t += sblk[p][tid];
        g_partS[blockIdx.x * NS + tid] = t;
    }
}

// ---------------- K_slot1: reduce partials + Wv -> updates (grid=NS, 1024 thr) ----------------
__global__ void __launch_bounds__(1024)
k_slot1(const float* __restrict__ Wv, const float* __restrict__ bv) {
    __shared__ __align__(16) float un_s[D];
    __shared__ float red[32];
    const int n = blockIdx.x, t = threadIdx.x;
    const int j = t >> 2, kq = t & 3;

    // U: 4 threads per column, 37 block-partials each
    {
        float a = 0.0f;
        const int base = kq * 37;
#pragma unroll
        for (int i = 0; i < 37; i++)
            a += g_partU[(size_t)(base + i) * (NS * D) + n * D + j];
        a += __shfl_xor_sync(0xffffffffu, a, 1);
        a += __shfl_xor_sync(0xffffffffu, a, 2);
        if (kq == 0) un_s[j] = a;
    }
    const float sv = (t < GRID_ACC) ? g_partS[t * NS + n] : 0.0f;
    const float S = block_sum1024(sv, red);  // internal syncs make un_s visible

    const float v = fc_dot(Wv, un_s, j, kq);
    if (kq == 0) g_updates[n * D + j] = v / S + bv[j];
}

// ---------------- K_gates: GRU gate GEMVs spread across chip (grid (NS,24)) ----------------
__global__ void __launch_bounds__(256)
k_gates(const float* __restrict__ W_ih, const float* __restrict__ W_hh,
        const float* __restrict__ b_ih, const float* __restrict__ b_hh) {
    __shared__ __align__(16) float in_s[D];
    const int n = blockIdx.x, y = blockIdx.y, tid = threadIdx.x;
    const bool is_x = (y < 12);
    const float* in = is_x ? (g_updates + n * D) : (g_slots + n * D);
    const float* W = is_x ? W_ih : W_hh;
    const float* bias = is_x ? b_ih : b_hh;
    float* out = is_x ? g_gx : g_gh;
    const int jbase = (is_x ? y : (y - 12)) * 64;

    in_s[tid] = in[tid];
    __syncthreads();

    const int j = jbase + (tid >> 2);
    const int kq = tid & 3;
    const float v = fc_dot(W, in_s, j, kq);
    if (kq == 0) out[n * 3 * D + j] = v + bias[j];
}

// ---------------- K_ff1: GRU combine + LN inline, then hidden = relu(W1@lnf+b1) ----------------
__global__ void __launch_bounds__(256)
k_ff1(const float* __restrict__ W1, const float* __restrict__ b1,
      const float* __restrict__ gf, const float* __restrict__ bef) {
    __shared__ __align__(16) float in_s[D];
    __shared__ float red[32];
    const int n = blockIdx.x, tid = threadIdx.x;

    // GRU combine (duplicated across the 4 y-blocks; deterministic)
    const float h = g_slots[n * D + tid];
    const float r = sigmoidf_(g_gx[n * 3 * D + tid] + g_gh[n * 3 * D + tid]);
    const float z = sigmoidf_(g_gx[n * 3 * D + D + tid] + g_gh[n * 3 * D + D + tid]);
    const float nn = tanhf(g_gx[n * 3 * D + 2 * D + tid] + r * g_gh[n * 3 * D + 2 * D + tid]);
    const float hnew = (1.0f - z) * nn + z * h;
    if (blockIdx.y == 0) g_hnew[n * D + tid] = hnew;

    // LN(hnew) -> in_s
    const float m = block_sum256(hnew, red) * (1.0f / (float)D);
    const float dv = hnew - m;
    const float var = block_sum256(dv * dv, red) * (1.0f / (float)D);
    in_s[tid] = dv * rsqrtf(var + LN_EPS) * gf[tid] + bef[tid];
    __syncthreads();

    const int j = blockIdx.y * 64 + (tid >> 2);
    const int kq = tid & 3;
    const float v = fc_dot(W1, in_s, j, kq);
    if (kq == 0) g_hd[n * D + j] = fmaxf(v + b1[j], 0.0f);
}

// ---------------- K_ff2: res = hnew + W2 @ hidden + b2 -> slots (+out) ----------------
__global__ void k_ff2(const float* __restrict__ W2, const float* __restrict__ b2,
                      float* __restrict__ out, int write_out) {
    __shared__ __align__(16) float in_s[D];
    const int n = blockIdx.x, tid = threadIdx.x;
    in_s[tid] = g_hd[n * D + tid];
    __syncthreads();
    const int j = blockIdx.y * 64 + (tid >> 2);
    const int kq = tid & 3;
    const float v = fc_dot(W2, in_s, j, kq);
    if (kq == 0) {
        const float res = g_hnew[n * D + j] + v + b2[j];
        g_slots[n * D + j] = res;
        if (write_out) out[n * D + j] = res;
    }
}

// ---------------- K_prep: LN(slots) -> q -> qk, cn (grid=NS, 1024 thr) ----------------
__global__ void __launch_bounds__(1024)
k_prep(const float* __restrict__ Wq, const float* __restrict__ bq,
       const float* __restrict__ bk,
       const float* __restrict__ gs, const float* __restrict__ bes) {
    __shared__ __align__(16) float h_s[D];
    __shared__ __align__(16) float s_s[D];
    __shared__ __align__(16) float q_s[D];
    __shared__ float red[32];
    const int n = blockIdx.x, t = threadIdx.x;

    if (t < D) h_s[t] = g_slots[n * D + t];
    __syncthreads();
    ln256_1024(h_s, s_s, gs, bes, red);
    q_qk_1024(n, s_s, q_s, Wq, bq, bk, red);
}

// ---------------- launch ----------------
extern "C" void kernel_launch(void* const* d_in, const int* in_sizes, int n_in,
                              void* d_out, int out_size) {
    const float* x      = (const float*)d_in[0];
    const float* noise  = (const float*)d_in[1];
    const float* mu     = (const float*)d_in[2];
    const float* sigma  = (const float*)d_in[3];
    const float* Wq     = (const float*)d_in[4];
    const float* bq     = (const float*)d_in[5];
    const float* Wk     = (const float*)d_in[6];
    const float* bk     = (const float*)d_in[7];
    const float* Wv     = (const float*)d_in[8];
    const float* bv     = (const float*)d_in[9];
    const float* W_ih   = (const float*)d_in[10];
    const float* W_hh   = (const float*)d_in[11];
    const float* b_ih   = (const float*)d_in[12];
    const float* b_hh   = (const float*)d_in[13];
    const float* W1     = (const float*)d_in[14];
    const float* b1     = (const float*)d_in[15];
    const float* W2     = (const float*)d_in[16];
    const float* b2     = (const float*)d_in[17];
    const float* g_in   = (const float*)d_in[18];
    const float* be_in  = (const float*)d_in[19];
    const float* g_s    = (const float*)d_in[20];
    const float* be_s   = (const float*)d_in[21];
    const float* g_f    = (const float*)d_in[22];
    const float* be_f   = (const float*)d_in[23];
    float* out = (float*)d_out;

    k_lnx<<<1024, 256>>>(x, g_in, be_in);
    k_wkT<<<dim3(8, 8), dim3(32, 8)>>>(Wk);
    k_init<<<NS, 1024>>>(noise, mu, sigma, Wq, bq, bk, g_s, be_s);

    for (int it = 0; it < 3; it++) {
        k_dots<<<GRID_DOTS, 256>>>();
        k_accum<<<GRID_ACC, 256>>>();
        k_slot1<<<NS, 1024>>>(Wv, bv);
        k_gates<<<dim3(NS, 24), 256>>>(W_ih, W_hh, b_ih, b_hh);
        k_ff1<<<dim3(NS, 4), 256>>>(W1, b1, g_f, be_f);
        k_ff2<<<dim3(NS, 4), 256>>>(W2, b2, out, it == 2 ? 1 : 0);
        if (it < 2) k_prep<<<NS, 1024>>>(Wq, bq, bk, g_s, be_s);
    }
}

// round 15
// speedup vs baseline: 1.1602x; 1.1602x over previous
#include <cuda_runtime.h>
#include <cuda_bf16.h>

#define D 256
#define NS 16
#define B_ROWS 131072
#define GRID_DOTS 296
#define TOTW_DOTS (GRID_DOTS * 8)
#define GRID_ACC 148
#define TOTW_ACC (GRID_ACC * 8)
#define LN_EPS 1e-5f
#define ATT_EPS 1e-8f
#define SCALE 0.0625f

typedef unsigned long long ull;

// ---------------- device scratch (static; no runtime allocation) ----------------
__device__ float g_xln[(size_t)B_ROWS * D];   // LN(x), materialized once
__device__ float g_WkT[D * D];                // Wk transposed
__device__ float g_slots[NS * D];
__device__ float g_qk[NS * D];
__device__ float g_cn[NS];
__device__ float g_attn[(size_t)B_ROWS * NS];
__device__ float g_partU[GRID_ACC * NS * D];
__device__ float g_partS[GRID_ACC * NS];
__device__ float g_updates[NS * D];
__device__ float g_gx[NS * 3 * D];
__device__ float g_gh[NS * 3 * D];
__device__ float g_hnew[NS * D];
__device__ float g_lnf[NS * D];
__device__ float g_hd[NS * D];

// ---------------- helpers ----------------
__device__ __forceinline__ float warp_sum(float v) {
    v += __shfl_xor_sync(0xffffffffu, v, 16);
    v += __shfl_xor_sync(0xffffffffu, v, 8);
    v += __shfl_xor_sync(0xffffffffu, v, 4);
    v += __shfl_xor_sync(0xffffffffu, v, 2);
    v += __shfl_xor_sync(0xffffffffu, v, 1);
    return v;
}

// blockDim.x == 256
__device__ __forceinline__ float block_sum256(float v, float* red) {
    const int lane = threadIdx.x & 31;
    const int w = threadIdx.x >> 5;
    v = warp_sum(v);
    if (lane == 0) red[w] = v;
    __syncthreads();
    if (w == 0) {
        float x = (lane < 8) ? red[lane] : 0.0f;
        x += __shfl_xor_sync(0xffffffffu, x, 4);
        x += __shfl_xor_sync(0xffffffffu, x, 2);
        x += __shfl_xor_sync(0xffffffffu, x, 1);
        if (lane == 0) red[0] = x;
    }
    __syncthreads();
    float r = red[0];
    __syncthreads();
    return r;
}

// blockDim.x == 1024 (threads without data pass 0)
__device__ __forceinline__ float block_sum1024(float v, float* red) {
    const int lane = threadIdx.x & 31;
    const int w = threadIdx.x >> 5;
    v = warp_sum(v);
    if (lane == 0) red[w] = v;
    __syncthreads();
    if (w == 0) {
        float x = red[lane];
        x = warp_sum(x);
        if (lane == 0) red[0] = x;
    }
    __syncthreads();
    float r = red[0];
    __syncthreads();
    return r;
}

__device__ __forceinline__ float dot4(float4 a, float4 b) {
    return a.x * b.x + a.y * b.y + a.z * b.z + a.w * b.w;
}

__device__ __forceinline__ ull pack2(float lo, float hi) {
    ull r;
    asm("mov.b64 %0, {%1, %2};" : "=l"(r) : "f"(lo), "f"(hi));
    return r;
}
__device__ __forceinline__ void unpack2(ull v, float& lo, float& hi) {
    asm("mov.b64 {%0, %1}, %2;" : "=f"(lo), "=f"(hi) : "l"(v));
}
__device__ __forceinline__ void fma2(ull& d, ull a, ull b) {
    asm("fma.rn.f32x2 %0, %1, %2, %0;" : "+l"(d) : "l"(a), "l"(b));
}
__device__ __forceinline__ ull add2(ull a, ull b) {
    ull r;
    asm("add.rn.f32x2 %0, %1, %2;" : "=l"(r) : "l"(a), "l"(b));
    return r;
}
__device__ __forceinline__ ull shfl_xor_u64(ull v, int m) {
    unsigned lo = (unsigned)v, hi = (unsigned)(v >> 32);
    lo = __shfl_xor_sync(0xffffffffu, lo, m);
    hi = __shfl_xor_sync(0xffffffffu, hi, m);
    return ((ull)hi << 32) | lo;
}

__device__ __forceinline__ float sigmoidf_(float x) { return 1.0f / (1.0f + expf(-x)); }

// quad-split dot: thread (j = t>>2, kq = t&3) dots W[j, kq*64 .. +63] with in_s;
// quad-reduced result valid in all 4 lanes of the quad.
__device__ __forceinline__ float fc_dot(const float* __restrict__ W, const float* in_s,
                                        int j, int kq) {
    const float4* w4 = reinterpret_cast<const float4*>(W + (size_t)j * D + kq * 64);
    const float4* s4 = reinterpret_cast<const float4*>(in_s + kq * 64);
    float a0 = 0.0f, a1 = 0.0f, a2 = 0.0f, a3 = 0.0f;
#pragma unroll
    for (int i = 0; i < 16; i += 4) {
        a0 += dot4(w4[i], s4[i]);
        a1 += dot4(w4[i + 1], s4[i + 1]);
        a2 += dot4(w4[i + 2], s4[i + 2]);
        a3 += dot4(w4[i + 3], s4[i + 3]);
    }
    float v = (a0 + a1) + (a2 + a3);
    v += __shfl_xor_sync(0xffffffffu, v, 1);
    v += __shfl_xor_sync(0xffffffffu, v, 2);
    return v;
}

// LN(src[0..255]) -> dst, for 1024-thread blocks (t<256 active); all threads call.
__device__ __forceinline__ void ln256_1024(const float* src, float* dst,
                                           const float* __restrict__ g,
                                           const float* __restrict__ be, float* red) {
    const int t = threadIdx.x;
    const float sv = (t < D) ? src[t] : 0.0f;
    const float m = block_sum1024(sv, red) * (1.0f / (float)D);
    const float dv = sv - m;
    const float var = block_sum1024((t < D) ? dv * dv : 0.0f, red) * (1.0f / (float)D);
    const float rstd = rsqrtf(var + LN_EPS);
    if (t < D) dst[t] = dv * rstd * g[t] + be[t];
    __syncthreads();
}

// q = Wq@s + bq ; qk = SCALE * q @ WkT ; cn = SCALE * q.bk   (1024-thread block, slot n)
__device__ __forceinline__ void q_qk_1024(int n, const float* s_s, float* q_s,
                                          const float* __restrict__ Wq, const float* __restrict__ bq,
                                          const float* __restrict__ bk, float* red) {
    const int t = threadIdx.x;
    const int j = t >> 2, kq = t & 3;
    const float qv = fc_dot(Wq, s_s, j, kq);
    if (kq == 0) q_s[j] = qv + bq[j];
    __syncthreads();
    const float kv = fc_dot(g_WkT, q_s, j, kq);
    if (kq == 0) g_qk[n * D + j] = kv * SCALE;
    const float p = block_sum1024((t < D) ? q_s[t] * bk[t] : 0.0f, red);
    if (t == 0) g_cn[n] = p * SCALE;
}

// ---------------- K: materialize LN(x) once ----------------
__global__ void __launch_bounds__(256)
k_lnx(const float* __restrict__ x,
      const float* __restrict__ gin, const float* __restrict__ bin) {
    const int lane = threadIdx.x & 31;
    const int warp = threadIdx.x >> 5;
    const float4* gin4 = reinterpret_cast<const float4*>(gin);
    const float4* bin4 = reinterpret_cast<const float4*>(bin);
    const float4 gv0 = gin4[lane], gv1 = gin4[lane + 32];
    const float4 bb0 = bin4[lane], bb1 = bin4[lane + 32];

    const float4* x4 = reinterpret_cast<const float4*>(x);
    float4* o4 = reinterpret_cast<float4*>(g_xln);
    const int gw = blockIdx.x * 8 + warp;

    for (int r = gw; r < B_ROWS; r += 1024 * 8) {
        const float4 v0 = x4[(size_t)r * 64 + lane];
        const float4 v1 = x4[(size_t)r * 64 + 32 + lane];
        float sm = v0.x + v0.y + v0.z + v0.w + v1.x + v1.y + v1.z + v1.w;
        float sq = v0.x * v0.x + v0.y * v0.y + v0.z * v0.z + v0.w * v0.w
                 + v1.x * v1.x + v1.y * v1.y + v1.z * v1.z + v1.w * v1.w;
        sm = warp_sum(sm);
        sq = warp_sum(sq);
        const float mean = sm * (1.0f / 256.0f);
        const float var = fmaxf(sq * (1.0f / 256.0f) - mean * mean, 0.0f);
        const float rstd = rsqrtf(var + LN_EPS);
        float4 w0, w1;
        w0.x = (v0.x - mean) * rstd * gv0.x + bb0.x;
        w0.y = (v0.y - mean) * rstd * gv0.y + bb0.y;
        w0.z = (v0.z - mean) * rstd * gv0.z + bb0.z;
        w0.w = (v0.w - mean) * rstd * gv0.w + bb0.w;
        w1.x = (v1.x - mean) * rstd * gv1.x + bb1.x;
        w1.y = (v1.y - mean) * rstd * gv1.y + bb1.y;
        w1.z = (v1.z - mean) * rstd * gv1.z + bb1.z;
        w1.w = (v1.w - mean) * rstd * gv1.w + bb1.w;
        o4[(size_t)r * 64 + lane] = w0;
        o4[(size_t)r * 64 + 32 + lane] = w1;
    }
}

// ---------------- K: transpose Wk (once) ----------------
__global__ void k_wkT(const float* __restrict__ Wk) {
    __shared__ float tile[32][33];
    const int tx = threadIdx.x, ty = threadIdx.y;
    const int xi = blockIdx.x * 32 + tx;
#pragma unroll
    for (int r = 0; r < 32; r += 8)
        tile[ty + r][tx] = Wk[(size_t)(blockIdx.y * 32 + ty + r) * D + xi];
    __syncthreads();
    const int xo = blockIdx.y * 32 + tx;
#pragma unroll
    for (int r = 0; r < 32; r += 8)
        g_WkT[(size_t)(blockIdx.x * 32 + ty + r) * D + xo] = tile[tx][ty + r];
}

// ---------------- K: slots init + LN + q + qk (grid=NS, block=1024) ----------------
__global__ void __launch_bounds__(1024)
k_init(const float* __restrict__ noise, const float* __restrict__ mu,
       const float* __restrict__ sigma,
       const float* __restrict__ Wq, const float* __restrict__ bq,
       const float* __restrict__ bk,
       const float* __restrict__ gs, const float* __restrict__ bes) {
    __shared__ __align__(16) float h_s[D];
    __shared__ __align__(16) float s_s[D];
    __shared__ __align__(16) float q_s[D];
    __shared__ float red[32];
    const int n = blockIdx.x, t = threadIdx.x;

    if (t < D) {
        const float sv = mu[t] + sigma[t] * noise[n * D + t];
        g_slots[n * D + t] = sv;
        h_s[t] = sv;
    }
    __syncthreads();
    ln256_1024(h_s, s_s, gs, bes, red);
    q_qk_1024(n, s_s, q_s, Wq, bq, bk, red);
}

// ---------------- K_dots: 2 rows per qk pass (packed), softmax -> attn ----------------
__global__ void __launch_bounds__(256, 2)
k_dots() {
    __shared__ __align__(16) float qk_s[NS * D];
    __shared__ float cn_s[NS];

    const int tid = threadIdx.x;
    const int lane = tid & 31;
    const int warp = tid >> 5;
    const int sigma = __brev((unsigned)(lane & 15)) >> 28;  // bitrev4

    for (int i = tid; i < NS * D; i += 256) qk_s[i] = g_qk[i];
    if (tid < NS) cn_s[tid] = g_cn[tid];
    __syncthreads();
    const float cn_r = cn_s[sigma];

    const float4* x4 = reinterpret_cast<const float4*>(g_xln);
    const float4* qk4 = reinterpret_cast<const float4*>(qk_s);

    for (int r0 = (blockIdx.x * 8 + warp) * 2; r0 < B_ROWS; r0 += 2 * TOTW_DOTS) {
        // anti-hoist: keep the loop-invariant qk_s LDS loads INSIDE the loop so
        // ptxas does not promote 2KB of qk into registers (cap+spill failure mode)
        asm volatile("" ::: "memory");

        // load rows r0 and r0+1 (r0 even, so r0+1 < B_ROWS always)
        const float4 a0 = x4[(size_t)r0 * 64 + lane];
        const float4 a1 = x4[(size_t)r0 * 64 + 32 + lane];
        const float4 b0 = x4[(size_t)(r0 + 1) * 64 + lane];
        const float4 b1 = x4[(size_t)(r0 + 1) * 64 + 32 + lane];

        const ull xa0 = pack2(a0.x, a0.y), xa1 = pack2(a0.z, a0.w);
        const ull xa2 = pack2(a1.x, a1.y), xa3 = pack2(a1.z, a1.w);
        const ull xb0 = pack2(b0.x, b0.y), xb1 = pack2(b0.z, b0.w);
        const ull xb2 = pack2(b1.x, b1.y), xb3 = pack2(b1.z, b1.w);

        // ---- 16 dots for BOTH rows with ONE qk read ----
        ull D2[NS];  // (dA, dB) packed per slot
#pragma unroll
        for (int n = 0; n < NS; n++) {
            const float4 qa = qk4[n * 64 + lane];
            const float4 qb = qk4[n * 64 + 32 + lane];
            const ull q0 = pack2(qa.x, qa.y), q1 = pack2(qa.z, qa.w);
            const ull q2 = pack2(qb.x, qb.y), q3 = pack2(qb.z, qb.w);
            ull accA = 0ull, accB = 0ull;
            fma2(accA, q0, xa0); fma2(accB, q0, xb0);
            fma2(accA, q1, xa1); fma2(accB, q1, xb1);
            fma2(accA, q2, xa2); fma2(accB, q2, xb2);
            fma2(accA, q3, xa3); fma2(accB, q3, xb3);
            float lA, hA, lB, hB;
            unpack2(accA, lA, hA);
            unpack2(accB, lB, hB);
            D2[n] = pack2(lA + hA, lB + hB);
        }

        // ---- packed halving butterfly: lane l ends with slot bitrev4(l&15), both rows ----
#pragma unroll
        for (int i = 0; i < 8; i++) {
            const ull sent = (lane & 1) ? D2[i] : D2[i + 8];
            const ull recv = shfl_xor_u64(sent, 1);
            D2[i] = add2((lane & 1) ? D2[i + 8] : D2[i], recv);
        }
#pragma unroll
        for (int i = 0; i < 4; i++) {
            const ull sent = (lane & 2) ? D2[i] : D2[i + 4];
            const ull recv = shfl_xor_u64(sent, 2);
            D2[i] = add2((lane & 2) ? D2[i + 4] : D2[i], recv);
        }
#pragma unroll
        for (int i = 0; i < 2; i++) {
            const ull sent = (lane & 4) ? D2[i] : D2[i + 2];
            const ull recv = shfl_xor_u64(sent, 4);
            D2[i] = add2((lane & 4) ? D2[i + 2] : D2[i], recv);
        }
        {
            const ull sent = (lane & 8) ? D2[0] : D2[1];
            const ull recv = shfl_xor_u64(sent, 8);
            D2[0] = add2((lane & 8) ? D2[1] : D2[0], recv);
        }
        D2[0] = add2(D2[0], shfl_xor_u64(D2[0], 16));

        float ddA, ddB;
        unpack2(D2[0], ddA, ddB);
        ddA += cn_r;
        ddB += cn_r;

        // ---- softmax across the 16 slots, both rows ----
        float mA = ddA, mB = ddB;
#pragma unroll
        for (int ofs = 1; ofs < 16; ofs <<= 1) {
            mA = fmaxf(mA, __shfl_xor_sync(0xffffffffu, mA, ofs));
            mB = fmaxf(mB, __shfl_xor_sync(0xffffffffu, mB, ofs));
        }
        const float eA = __expf(ddA - mA);
        const float eB = __expf(ddB - mB);
        float sA = eA, sB = eB;
#pragma unroll
        for (int ofs = 1; ofs < 16; ofs <<= 1) {
            sA += __shfl_xor_sync(0xffffffffu, sA, ofs);
            sB += __shfl_xor_sync(0xffffffffu, sB, ofs);
        }
        const float aA = __fdividef(eA, sA) + ATT_EPS;
        const float aB = __fdividef(eB, sB) + ATT_EPS;

        if (lane < 16) {
            g_attn[(size_t)r0 * NS + sigma] = aA;
            g_attn[(size_t)(r0 + 1) * NS + sigma] = aB;
        }
    }
}

// ---------------- K_accum: occ-1 full-row accumulators + 4-row unroll; S partials ----
__global__ void __launch_bounds__(256, 1)
k_accum() {
    __shared__ __align__(16) float ublk[NS * D];
    __shared__ float sblk[8][NS];

    const int tid = threadIdx.x;
    const int lane = tid & 31;
    const int warp = tid >> 5;

    ull u2[NS][4];
#pragma unroll
    for (int n = 0; n < NS; n++)
#pragma unroll
        for (int p = 0; p < 4; p++) u2[n][p] = 0ull;
    float s_acc[NS];
#pragma unroll
    for (int n = 0; n < NS; n++) s_acc[n] = 0.0f;

    const float4* x4 = reinterpret_cast<const float4*>(g_xln);
    const float4* ag4 = reinterpret_cast<const float4*>(g_attn);

    // 4 rows per pass (r0 multiple of 4; B_ROWS divisible by 4 -> r0+3 always valid)
    for (int r0 = (blockIdx.x * 8 + warp) * 4; r0 < B_ROWS; r0 += 4 * TOTW_ACC) {
        // ---- xln for all 4 rows upfront: 8 independent LDG.128 ----
        const float4 a0 = x4[(size_t)r0 * 64 + lane];
        const float4 a1 = x4[(size_t)r0 * 64 + 32 + lane];
        const float4 b0 = x4[(size_t)(r0 + 1) * 64 + lane];
        const float4 b1 = x4[(size_t)(r0 + 1) * 64 + 32 + lane];
        const float4 c0 = x4[(size_t)(r0 + 2) * 64 + lane];
        const float4 c1 = x4[(size_t)(r0 + 2) * 64 + 32 + lane];
        const float4 d0 = x4[(size_t)(r0 + 3) * 64 + lane];
        const float4 d1 = x4[(size_t)(r0 + 3) * 64 + 32 + lane];

        const ull xa0 = pack2(a0.x, a0.y), xa1 = pack2(a0.z, a0.w);
        const ull xa2 = pack2(a1.x, a1.y), xa3 = pack2(a1.z, a1.w);
        const ull xb0 = pack2(b0.x, b0.y), xb1 = pack2(b0.z, b0.w);
        const ull xb2 = pack2(b1.x, b1.y), xb3 = pack2(b1.z, b1.w);
        const ull xc0 = pack2(c0.x, c0.y), xc1 = pack2(c0.z, c0.w);
        const ull xc2 = pack2(c1.x, c1.y), xc3 = pack2(c1.z, c1.w);
        const ull xd0 = pack2(d0.x, d0.y), xd1 = pack2(d0.z, d0.w);
        const ull xd2 = pack2(d1.x, d1.y), xd3 = pack2(d1.z, d1.w);

        // ---- attn rows 0,1; FMA; then attn rows 2,3; FMA (bounds register pressure) ----
        {
            const float4 af0 = ag4[(size_t)r0 * 4 + 0];
            const float4 af1 = ag4[(size_t)r0 * 4 + 1];
            const float4 af2 = ag4[(size_t)r0 * 4 + 2];
            const float4 af3 = ag4[(size_t)r0 * 4 + 3];
            const float4 bf0 = ag4[(size_t)(r0 + 1) * 4 + 0];
            const float4 bf1 = ag4[(size_t)(r0 + 1) * 4 + 1];
            const float4 bf2 = ag4[(size_t)(r0 + 1) * 4 + 2];
            const float4 bf3 = ag4[(size_t)(r0 + 1) * 4 + 3];
            const float av[NS] = {af0.x, af0.y, af0.z, af0.w, af1.x, af1.y, af1.z, af1.w,
                                  af2.x, af2.y, af2.z, af2.w, af3.x, af3.y, af3.z, af3.w};
            const float bv[NS] = {bf0.x, bf0.y, bf0.z, bf0.w, bf1.x, bf1.y, bf1.z, bf1.w,
                                  bf2.x, bf2.y, bf2.z, bf2.w, bf3.x, bf3.y, bf3.z, bf3.w};
#pragma unroll
            for (int n = 0; n < NS; n++) {
                s_acc[n] += av[n] + bv[n];
                const ull a2 = pack2(av[n], av[n]);
                fma2(u2[n][0], a2, xa0);
                fma2(u2[n][1], a2, xa1);
                fma2(u2[n][2], a2, xa2);
                fma2(u2[n][3], a2, xa3);
                const ull b2v = pack2(bv[n], bv[n]);
                fma2(u2[n][0], b2v, xb0);
                fma2(u2[n][1], b2v, xb1);
                fma2(u2[n][2], b2v, xb2);
                fma2(u2[n][3], b2v, xb3);
            }
        }
        {
            const float4 cf0 = ag4[(size_t)(r0 + 2) * 4 + 0];
            const float4 cf1 = ag4[(size_t)(r0 + 2) * 4 + 1];
            const float4 cf2 = ag4[(size_t)(r0 + 2) * 4 + 2];
            const float4 cf3 = ag4[(size_t)(r0 + 2) * 4 + 3];
            const float4 df0 = ag4[(size_t)(r0 + 3) * 4 + 0];
            const float4 df1 = ag4[(size_t)(r0 + 3) * 4 + 1];
            const float4 df2 = ag4[(size_t)(r0 + 3) * 4 + 2];
            const float4 df3 = ag4[(size_t)(r0 + 3) * 4 + 3];
            const float cv[NS] = {cf0.x, cf0.y, cf0.z, cf0.w, cf1.x, cf1.y, cf1.z, cf1.w,
                                  cf2.x, cf2.y, cf2.z, cf2.w, cf3.x, cf3.y, cf3.z, cf3.w};
            const float dv[NS] = {df0.x, df0.y, df0.z, df0.w, df1.x, df1.y, df1.z, df1.w,
                                  df2.x, df2.y, df2.z, df2.w, df3.x, df3.y, df3.z, df3.w};
#pragma unroll
            for (int n = 0; n < NS; n++) {
                s_acc[n] += cv[n] + dv[n];
                const ull c2 = pack2(cv[n], cv[n]);
                fma2(u2[n][0], c2, xc0);
                fma2(u2[n][1], c2, xc1);
                fma2(u2[n][2], c2, xc2);
                fma2(u2[n][3], c2, xc3);
                const ull d2v = pack2(dv[n], dv[n]);
                fma2(u2[n][0], d2v, xd0);
                fma2(u2[n][1], d2v, xd1);
                fma2(u2[n][2], d2v, xd2);
                fma2(u2[n][3], d2v, xd3);
            }
        }
    }

    // stage per-warp partials into shared (serialized, deterministic)
    for (int w = 0; w < 8; w++) {
        if (warp == w) {
#pragma unroll
            for (int n = 0; n < NS; n++) {
#pragma unroll
                for (int p = 0; p < 4; p++) {
                    float lo, hi;
                    unpack2(u2[n][p], lo, hi);
                    const int c = (p < 2) ? (lane * 4 + 2 * p) : (128 + lane * 4 + 2 * (p - 2));
                    if (w == 0) {
                        ublk[n * D + c] = lo;
                        ublk[n * D + c + 1] = hi;
                    } else {
                        ublk[n * D + c] += lo;
                        ublk[n * D + c + 1] += hi;
                    }
                }
            }
            if (lane == 0) {
#pragma unroll
                for (int n = 0; n < NS; n++) sblk[w][n] = s_acc[n];
            }
        }
        __syncthreads();
    }

    for (int i = tid; i < NS * D; i += 256)
        g_partU[(size_t)blockIdx.x * (NS * D) + i] = ublk[i];
    if (tid < NS) {
        float t = 0.0f;
#pragma unroll
        for (int w = 0; w < 8; w++) t += sblk[w][tid];
        g_partS[blockIdx.x * NS + tid] = t;
    }
}

// ---------------- K_slot1: reduce partials + Wv -> updates (grid=NS, 1024 thr) ----------------
__global__ void __launch_bounds__(1024)
k_slot1(const float* __restrict__ Wv, const float* __restrict__ bv) {
    __shared__ __align__(16) float un_s[D];
    __shared__ float red[32];
    const int n = blockIdx.x, t = threadIdx.x;
    const int j = t >> 2, kq = t & 3;

    // U: 4 threads per column, 37 block-partials each
    {
        float a = 0.0f;
        const int base = kq * 37;
#pragma unroll
        for (int i = 0; i < 37; i++)
            a += g_partU[(size_t)(base + i) * (NS * D) + n * D + j];
        a += __shfl_xor_sync(0xffffffffu, a, 1);
        a += __shfl_xor_sync(0xffffffffu, a, 2);
        if (kq == 0) un_s[j] = a;
    }
    const float sv = (t < GRID_ACC) ? g_partS[t * NS + n] : 0.0f;
    const float S = block_sum1024(sv, red);  // internal syncs make un_s visible

    const float v = fc_dot(Wv, un_s, j, kq);
    if (kq == 0) g_updates[n * D + j] = v / S + bv[j];
}

// ---------------- K_gates: GRU gate GEMVs spread across chip (grid (NS,24)) ----------------
__global__ void __launch_bounds__(256)
k_gates(const float* __restrict__ W_ih, const float* __restrict__ W_hh,
        const float* __restrict__ b_ih, const float* __restrict__ b_hh) {
    __shared__ __align__(16) float in_s[D];
    const int n = blockIdx.x, y = blockIdx.y, tid = threadIdx.x;
    const bool is_x = (y < 12);
    const float* in = is_x ? (g_updates + n * D) : (g_slots + n * D);
    const float* W = is_x ? W_ih : W_hh;
    const float* bias = is_x ? b_ih : b_hh;
    float* out = is_x ? g_gx : g_gh;
    const int jbase = (is_x ? y : (y - 12)) * 64;

    in_s[tid] = in[tid];
    __syncthreads();

    const int j = jbase + (tid >> 2);
    const int kq = tid & 3;
    const float v = fc_dot(W, in_s, j, kq);
    if (kq == 0) out[n * 3 * D + j] = v + bias[j];
}

// ---------------- K_gru_ln: GRU combine + LN ----------------
__global__ void k_gru_ln(const float* __restrict__ gf, const float* __restrict__ bef) {
    __shared__ float red[32];
    const int n = blockIdx.x, t = threadIdx.x;
    const float xr = g_gx[n * 3 * D + t];
    const float xz = g_gx[n * 3 * D + D + t];
    const float xn = g_gx[n * 3 * D + 2 * D + t];
    const float hr = g_gh[n * 3 * D + t];
    const float hz = g_gh[n * 3 * D + D + t];
    const float hn = g_gh[n * 3 * D + 2 * D + t];
    const float h = g_slots[n * D + t];

    const float r = sigmoidf_(xr + hr);
    const float z = sigmoidf_(xz + hz);
    const float nn = tanhf(xn + r * hn);
    const float hnew = (1.0f - z) * nn + z * h;

    const float m = block_sum256(hnew, red) * (1.0f / (float)D);
    const float dv = hnew - m;
    const float var = block_sum256(dv * dv, red) * (1.0f / (float)D);
    const float lnf = dv * rsqrtf(var + LN_EPS) * gf[t] + bef[t];

    g_hnew[n * D + t] = hnew;
    g_lnf[n * D + t] = lnf;
}

// ---------------- K_ff1: hidden = relu(W1 @ lnf + b1) ----------------
__global__ void k_ff1(const float* __restrict__ W1, const float* __restrict__ b1) {
    __shared__ __align__(16) float in_s[D];
    const int n = blockIdx.x, tid = threadIdx.x;
    in_s[tid] = g_lnf[n * D + tid];
    __syncthreads();
    const int j = blockIdx.y * 64 + (tid >> 2);
    const int kq = tid & 3;
    const float v = fc_dot(W1, in_s, j, kq);
    if (kq == 0) g_hd[n * D + j] = fmaxf(v + b1[j], 0.0f);
}

// ---------------- K_ff2: res = hnew + W2 @ hidden + b2 -> slots (+out) ----------------
__global__ void k_ff2(const float* __restrict__ W2, const float* __restrict__ b2,
                      float* __restrict__ out, int write_out) {
    __shared__ __align__(16) float in_s[D];
    const int n = blockIdx.x, tid = threadIdx.x;
    in_s[tid] = g_hd[n * D + tid];
    __syncthreads();
    const int j = blockIdx.y * 64 + (tid >> 2);
    const int kq = tid & 3;
    const float v = fc_dot(W2, in_s, j, kq);
    if (kq == 0) {
        const float res = g_hnew[n * D + j] + v + b2[j];
        g_slots[n * D + j] = res;
        if (write_out) out[n * D + j] = res;
    }
}

// ---------------- K_prep: LN(slots) -> q -> qk, cn (grid=NS, 1024 thr) ----------------
__global__ void __launch_bounds__(1024)
k_prep(const float* __restrict__ Wq, const float* __restrict__ bq,
       const float* __restrict__ bk,
       const float* __restrict__ gs, const float* __restrict__ bes) {
    __shared__ __align__(16) float h_s[D];
    __shared__ __align__(16) float s_s[D];
    __shared__ __align__(16) float q_s[D];
    __shared__ float red[32];
    const int n = blockIdx.x, t = threadIdx.x;

    if (t < D) h_s[t] = g_slots[n * D + t];
    __syncthreads();
    ln256_1024(h_s, s_s, gs, bes, red);
    q_qk_1024(n, s_s, q_s, Wq, bq, bk, red);
}

// ---------------- launch ----------------
extern "C" void kernel_launch(void* const* d_in, const int* in_sizes, int n_in,
                              void* d_out, int out_size) {
    const float* x      = (const float*)d_in[0];
    const float* noise  = (const float*)d_in[1];
    const float* mu     = (const float*)d_in[2];
    const float* sigma  = (const float*)d_in[3];
    const float* Wq     = (const float*)d_in[4];
    const float* bq     = (const float*)d_in[5];
    const float* Wk     = (const float*)d_in[6];
    const float* bk     = (const float*)d_in[7];
    const float* Wv     = (const float*)d_in[8];
    const float* bv     = (const float*)d_in[9];
    const float* W_ih   = (const float*)d_in[10];
    const float* W_hh   = (const float*)d_in[11];
    const float* b_ih   = (const float*)d_in[12];
    const float* b_hh   = (const float*)d_in[13];
    const float* W1     = (const float*)d_in[14];
    const float* b1     = (const float*)d_in[15];
    const float* W2     = (const float*)d_in[16];
    const float* b2     = (const float*)d_in[17];
    const float* g_in   = (const float*)d_in[18];
    const float* be_in  = (const float*)d_in[19];
    const float* g_s    = (const float*)d_in[20];
    const float* be_s   = (const float*)d_in[21];
    const float* g_f    = (const float*)d_in[22];
    const float* be_f   = (const float*)d_in[23];
    float* out = (float*)d_out;

    k_lnx<<<1024, 256>>>(x, g_in, be_in);
    k_wkT<<<dim3(8, 8), dim3(32, 8)>>>(Wk);
    k_init<<<NS, 1024>>>(noise, mu, sigma, Wq, bq, bk, g_s, be_s);

    for (int it = 0; it < 3; it++) {
        k_dots<<<GRID_DOTS, 256>>>();
        k_accum<<<GRID_ACC, 256>>>();
        k_slot1<<<NS, 1024>>>(Wv, bv);
        k_gates<<<dim3(NS, 24), 256>>>(W_ih, W_hh, b_ih, b_hh);
        k_gru_ln<<<NS, D>>>(g_f, be_f);
        k_ff1<<<dim3(NS, 4), 256>>>(W1, b1);
        k_ff2<<<dim3(NS, 4), 256>>>(W2, b2, out, it == 2 ? 1 : 0);
        if (it < 2) k_prep<<<NS, 1024>>>(Wq, bq, bk, g_s, be_s);
    }
}

// round 16
// speedup vs baseline: 1.2346x; 1.0642x over previous
#include <cuda_runtime.h>
#include <cuda_bf16.h>

#define D 256
#define NS 16
#define B_ROWS 131072
#define GRID_DOTS 296
#define TOTW_DOTS (GRID_DOTS * 8)
#define GRID_ACC 148
#define TOTW_ACC (GRID_ACC * 8)
#define LN_EPS 1e-5f
#define ATT_EPS 1e-8f
#define SCALE 0.0625f

typedef unsigned long long ull;

// ---------------- device scratch (static; no runtime allocation) ----------------
__device__ float g_xln[(size_t)B_ROWS * D];   // LN(x), materialized once
__device__ float g_WkT[D * D];                // Wk transposed
__device__ float g_slots[NS * D];
__device__ float g_qk[NS * D];
__device__ float g_cn[NS];
__device__ float g_attn[(size_t)B_ROWS * NS];
__device__ float g_partU[GRID_ACC * NS * D];
__device__ float g_partS[GRID_ACC * NS];
__device__ float g_updates[NS * D];
__device__ float g_gx[NS * 3 * D];
__device__ float g_gh[NS * 3 * D];
__device__ float g_hnew[NS * D];
__device__ float g_lnf[NS * D];
__device__ float g_hd[NS * D];

// ---------------- helpers ----------------
__device__ __forceinline__ float warp_sum(float v) {
    v += __shfl_xor_sync(0xffffffffu, v, 16);
    v += __shfl_xor_sync(0xffffffffu, v, 8);
    v += __shfl_xor_sync(0xffffffffu, v, 4);
    v += __shfl_xor_sync(0xffffffffu, v, 2);
    v += __shfl_xor_sync(0xffffffffu, v, 1);
    return v;
}

// blockDim.x == 256
__device__ __forceinline__ float block_sum256(float v, float* red) {
    const int lane = threadIdx.x & 31;
    const int w = threadIdx.x >> 5;
    v = warp_sum(v);
    if (lane == 0) red[w] = v;
    __syncthreads();
    if (w == 0) {
        float x = (lane < 8) ? red[lane] : 0.0f;
        x += __shfl_xor_sync(0xffffffffu, x, 4);
        x += __shfl_xor_sync(0xffffffffu, x, 2);
        x += __shfl_xor_sync(0xffffffffu, x, 1);
        if (lane == 0) red[0] = x;
    }
    __syncthreads();
    float r = red[0];
    __syncthreads();
    return r;
}

// blockDim.x == 1024 (threads without data pass 0)
__device__ __forceinline__ float block_sum1024(float v, float* red) {
    const int lane = threadIdx.x & 31;
    const int w = threadIdx.x >> 5;
    v = warp_sum(v);
    if (lane == 0) red[w] = v;
    __syncthreads();
    if (w == 0) {
        float x = red[lane];
        x = warp_sum(x);
        if (lane == 0) red[0] = x;
    }
    __syncthreads();
    float r = red[0];
    __syncthreads();
    return r;
}

__device__ __forceinline__ float dot4(float4 a, float4 b) {
    return a.x * b.x + a.y * b.y + a.z * b.z + a.w * b.w;
}

__device__ __forceinline__ ull pack2(float lo, float hi) {
    ull r;
    asm("mov.b64 %0, {%1, %2};" : "=l"(r) : "f"(lo), "f"(hi));
    return r;
}
__device__ __forceinline__ void unpack2(ull v, float& lo, float& hi) {
    asm("mov.b64 {%0, %1}, %2;" : "=f"(lo), "=f"(hi) : "l"(v));
}
__device__ __forceinline__ void fma2(ull& d, ull a, ull b) {
    asm("fma.rn.f32x2 %0, %1, %2, %0;" : "+l"(d) : "l"(a), "l"(b));
}
__device__ __forceinline__ ull add2(ull a, ull b) {
    ull r;
    asm("add.rn.f32x2 %0, %1, %2;" : "=l"(r) : "l"(a), "l"(b));
    return r;
}
__device__ __forceinline__ ull shfl_xor_u64(ull v, int m) {
    unsigned lo = (unsigned)v, hi = (unsigned)(v >> 32);
    lo = __shfl_xor_sync(0xffffffffu, lo, m);
    hi = __shfl_xor_sync(0xffffffffu, hi, m);
    return ((ull)hi << 32) | lo;
}

__device__ __forceinline__ float sigmoidf_(float x) { return 1.0f / (1.0f + expf(-x)); }

// quad-split dot: thread (j = t>>2, kq = t&3) dots W[j, kq*64 .. +63] with in_s;
// quad-reduced result valid in all 4 lanes of the quad.
__device__ __forceinline__ float fc_dot(const float* __restrict__ W, const float* in_s,
                                        int j, int kq) {
    const float4* w4 = reinterpret_cast<const float4*>(W + (size_t)j * D + kq * 64);
    const float4* s4 = reinterpret_cast<const float4*>(in_s + kq * 64);
    float a0 = 0.0f, a1 = 0.0f, a2 = 0.0f, a3 = 0.0f;
#pragma unroll
    for (int i = 0; i < 16; i += 4) {
        a0 += dot4(w4[i], s4[i]);
        a1 += dot4(w4[i + 1], s4[i + 1]);
        a2 += dot4(w4[i + 2], s4[i + 2]);
        a3 += dot4(w4[i + 3], s4[i + 3]);
    }
    float v = (a0 + a1) + (a2 + a3);
    v += __shfl_xor_sync(0xffffffffu, v, 1);
    v += __shfl_xor_sync(0xffffffffu, v, 2);
    return v;
}

// LN(src[0..255]) -> dst, for 1024-thread blocks (t<256 active); all threads call.
__device__ __forceinline__ void ln256_1024(const float* src, float* dst,
                                           const float* __restrict__ g,
                                           const float* __restrict__ be, float* red) {
    const int t = threadIdx.x;
    const float sv = (t < D) ? src[t] : 0.0f;
    const float m = block_sum1024(sv, red) * (1.0f / (float)D);
    const float dv = sv - m;
    const float var = block_sum1024((t < D) ? dv * dv : 0.0f, red) * (1.0f / (float)D);
    const float rstd = rsqrtf(var + LN_EPS);
    if (t < D) dst[t] = dv * rstd * g[t] + be[t];
    __syncthreads();
}

// q = Wq@s + bq ; qk = SCALE * q @ WkT ; cn = SCALE * q.bk   (1024-thread block, slot n)
__device__ __forceinline__ void q_qk_1024(int n, const float* s_s, float* q_s,
                                          const float* __restrict__ Wq, const float* __restrict__ bq,
                                          const float* __restrict__ bk, float* red) {
    const int t = threadIdx.x;
    const int j = t >> 2, kq = t & 3;
    const float qv = fc_dot(Wq, s_s, j, kq);
    if (kq == 0) q_s[j] = qv + bq[j];
    __syncthreads();
    const float kv = fc_dot(g_WkT, q_s, j, kq);
    if (kq == 0) g_qk[n * D + j] = kv * SCALE;
    const float p = block_sum1024((t < D) ? q_s[t] * bk[t] : 0.0f, red);
    if (t == 0) g_cn[n] = p * SCALE;
}

// ---------------- K: materialize LN(x) once ----------------
__global__ void __launch_bounds__(256)
k_lnx(const float* __restrict__ x,
      const float* __restrict__ gin, const float* __restrict__ bin) {
    const int lane = threadIdx.x & 31;
    const int warp = threadIdx.x >> 5;
    const float4* gin4 = reinterpret_cast<const float4*>(gin);
    const float4* bin4 = reinterpret_cast<const float4*>(bin);
    const float4 gv0 = gin4[lane], gv1 = gin4[lane + 32];
    const float4 bb0 = bin4[lane], bb1 = bin4[lane + 32];

    const float4* x4 = reinterpret_cast<const float4*>(x);
    float4* o4 = reinterpret_cast<float4*>(g_xln);
    const int gw = blockIdx.x * 8 + warp;

    for (int r = gw; r < B_ROWS; r += 1024 * 8) {
        const float4 v0 = x4[(size_t)r * 64 + lane];
        const float4 v1 = x4[(size_t)r * 64 + 32 + lane];
        float sm = v0.x + v0.y + v0.z + v0.w + v1.x + v1.y + v1.z + v1.w;
        float sq = v0.x * v0.x + v0.y * v0.y + v0.z * v0.z + v0.w * v0.w
                 + v1.x * v1.x + v1.y * v1.y + v1.z * v1.z + v1.w * v1.w;
        sm = warp_sum(sm);
        sq = warp_sum(sq);
        const float mean = sm * (1.0f / 256.0f);
        const float var = fmaxf(sq * (1.0f / 256.0f) - mean * mean, 0.0f);
        const float rstd = rsqrtf(var + LN_EPS);
        float4 w0, w1;
        w0.x = (v0.x - mean) * rstd * gv0.x + bb0.x;
        w0.y = (v0.y - mean) * rstd * gv0.y + bb0.y;
        w0.z = (v0.z - mean) * rstd * gv0.z + bb0.z;
        w0.w = (v0.w - mean) * rstd * gv0.w + bb0.w;
        w1.x = (v1.x - mean) * rstd * gv1.x + bb1.x;
        w1.y = (v1.y - mean) * rstd * gv1.y + bb1.y;
        w1.z = (v1.z - mean) * rstd * gv1.z + bb1.z;
        w1.w = (v1.w - mean) * rstd * gv1.w + bb1.w;
        o4[(size_t)r * 64 + lane] = w0;
        o4[(size_t)r * 64 + 32 + lane] = w1;
    }
}

// ---------------- K: transpose Wk (once) ----------------
__global__ void k_wkT(const float* __restrict__ Wk) {
    __shared__ float tile[32][33];
    const int tx = threadIdx.x, ty = threadIdx.y;
    const int xi = blockIdx.x * 32 + tx;
#pragma unroll
    for (int r = 0; r < 32; r += 8)
        tile[ty + r][tx] = Wk[(size_t)(blockIdx.y * 32 + ty + r) * D + xi];
    __syncthreads();
    const int xo = blockIdx.y * 32 + tx;
#pragma unroll
    for (int r = 0; r < 32; r += 8)
        g_WkT[(size_t)(blockIdx.x * 32 + ty + r) * D + xo] = tile[tx][ty + r];
}

// ---------------- K: slots init + LN + q + qk (grid=NS, block=1024) ----------------
__global__ void __launch_bounds__(1024)
k_init(const float* __restrict__ noise, const float* __restrict__ mu,
       const float* __restrict__ sigma,
       const float* __restrict__ Wq, const float* __restrict__ bq,
       const float* __restrict__ bk,
       const float* __restrict__ gs, const float* __restrict__ bes) {
    __shared__ __align__(16) float h_s[D];
    __shared__ __align__(16) float s_s[D];
    __shared__ __align__(16) float q_s[D];
    __shared__ float red[32];
    const int n = blockIdx.x, t = threadIdx.x;

    if (t < D) {
        const float sv = mu[t] + sigma[t] * noise[n * D + t];
        g_slots[n * D + t] = sv;
        h_s[t] = sv;
    }
    __syncthreads();
    ln256_1024(h_s, s_s, gs, bes, red);
    q_qk_1024(n, s_s, q_s, Wq, bq, bk, red);
}

// ---------------- K_dots: 4 rows per qk pass (2 packed arrays), softmax -> attn ----------------
__global__ void __launch_bounds__(256, 2)
k_dots() {
    __shared__ __align__(16) float qk_s[NS * D];
    __shared__ float cn_s[NS];

    const int tid = threadIdx.x;
    const int lane = tid & 31;
    const int warp = tid >> 5;
    const int sigma = __brev((unsigned)(lane & 15)) >> 28;  // bitrev4

    for (int i = tid; i < NS * D; i += 256) qk_s[i] = g_qk[i];
    if (tid < NS) cn_s[tid] = g_cn[tid];
    __syncthreads();
    const float cn_r = cn_s[sigma];

    const float4* x4 = reinterpret_cast<const float4*>(g_xln);
    const float4* qk4 = reinterpret_cast<const float4*>(qk_s);

    for (int r0 = (blockIdx.x * 8 + warp) * 4; r0 < B_ROWS; r0 += 4 * TOTW_DOTS) {
        // anti-hoist: keep the loop-invariant qk_s LDS loads INSIDE the loop so
        // ptxas does not promote 2KB of qk into registers (cap+spill failure mode)
        asm volatile("" ::: "memory");

        // rows r0..r0+3 (r0 multiple of 4; B_ROWS % 4 == 0)
        const float4 a0 = x4[(size_t)r0 * 64 + lane];
        const float4 a1 = x4[(size_t)r0 * 64 + 32 + lane];
        const float4 b0 = x4[(size_t)(r0 + 1) * 64 + lane];
        const float4 b1 = x4[(size_t)(r0 + 1) * 64 + 32 + lane];
        const float4 c0 = x4[(size_t)(r0 + 2) * 64 + lane];
        const float4 c1 = x4[(size_t)(r0 + 2) * 64 + 32 + lane];
        const float4 d0 = x4[(size_t)(r0 + 3) * 64 + lane];
        const float4 d1 = x4[(size_t)(r0 + 3) * 64 + 32 + lane];

        const ull xa0 = pack2(a0.x, a0.y), xa1 = pack2(a0.z, a0.w);
        const ull xa2 = pack2(a1.x, a1.y), xa3 = pack2(a1.z, a1.w);
        const ull xb0 = pack2(b0.x, b0.y), xb1 = pack2(b0.z, b0.w);
        const ull xb2 = pack2(b1.x, b1.y), xb3 = pack2(b1.z, b1.w);
        const ull xc0 = pack2(c0.x, c0.y), xc1 = pack2(c0.z, c0.w);
        const ull xc2 = pack2(c1.x, c1.y), xc3 = pack2(c1.z, c1.w);
        const ull xd0 = pack2(d0.x, d0.y), xd1 = pack2(d0.z, d0.w);
        const ull xd2 = pack2(d1.x, d1.y), xd3 = pack2(d1.z, d1.w);

        // ---- 16 dots for ALL FOUR rows with ONE qk read ----
        ull D2[NS];  // (dA, dB) packed per slot
        ull E2[NS];  // (dC, dD) packed per slot
#pragma unroll
        for (int n = 0; n < NS; n++) {
            const float4 qa = qk4[n * 64 + lane];
            const float4 qb = qk4[n * 64 + 32 + lane];
            const ull q0 = pack2(qa.x, qa.y), q1 = pack2(qa.z, qa.w);
            const ull q2 = pack2(qb.x, qb.y), q3 = pack2(qb.z, qb.w);
            ull accA = 0ull, accB = 0ull, accC = 0ull, accD = 0ull;
            fma2(accA, q0, xa0); fma2(accB, q0, xb0); fma2(accC, q0, xc0); fma2(accD, q0, xd0);
            fma2(accA, q1, xa1); fma2(accB, q1, xb1); fma2(accC, q1, xc1); fma2(accD, q1, xd1);
            fma2(accA, q2, xa2); fma2(accB, q2, xb2); fma2(accC, q2, xc2); fma2(accD, q2, xd2);
            fma2(accA, q3, xa3); fma2(accB, q3, xb3); fma2(accC, q3, xc3); fma2(accD, q3, xd3);
            float lA, hA, lB, hB, lC, hC, lD, hD;
            unpack2(accA, lA, hA);
            unpack2(accB, lB, hB);
            unpack2(accC, lC, hC);
            unpack2(accD, lD, hD);
            D2[n] = pack2(lA + hA, lB + hB);
            E2[n] = pack2(lC + hC, lD + hD);
        }

        // ---- packed halving butterfly on both arrays: lane l -> slot bitrev4(l&15) ----
#pragma unroll
        for (int i = 0; i < 8; i++) {
            const ull sD = (lane & 1) ? D2[i] : D2[i + 8];
            const ull sE = (lane & 1) ? E2[i] : E2[i + 8];
            const ull rD = shfl_xor_u64(sD, 1);
            const ull rE = shfl_xor_u64(sE, 1);
            D2[i] = add2((lane & 1) ? D2[i + 8] : D2[i], rD);
            E2[i] = add2((lane & 1) ? E2[i + 8] : E2[i], rE);
        }
#pragma unroll
        for (int i = 0; i < 4; i++) {
            const ull sD = (lane & 2) ? D2[i] : D2[i + 4];
            const ull sE = (lane & 2) ? E2[i] : E2[i + 4];
            const ull rD = shfl_xor_u64(sD, 2);
            const ull rE = shfl_xor_u64(sE, 2);
            D2[i] = add2((lane & 2) ? D2[i + 4] : D2[i], rD);
            E2[i] = add2((lane & 2) ? E2[i + 4] : E2[i], rE);
        }
#pragma unroll
        for (int i = 0; i < 2; i++) {
            const ull sD = (lane & 4) ? D2[i] : D2[i + 2];
            const ull sE = (lane & 4) ? E2[i] : E2[i + 2];
            const ull rD = shfl_xor_u64(sD, 4);
            const ull rE = shfl_xor_u64(sE, 4);
            D2[i] = add2((lane & 4) ? D2[i + 2] : D2[i], rD);
            E2[i] = add2((lane & 4) ? E2[i + 2] : E2[i], rE);
        }
        {
            const ull sD = (lane & 8) ? D2[0] : D2[1];
            const ull sE = (lane & 8) ? E2[0] : E2[1];
            const ull rD = shfl_xor_u64(sD, 8);
            const ull rE = shfl_xor_u64(sE, 8);
            D2[0] = add2((lane & 8) ? D2[1] : D2[0], rD);
            E2[0] = add2((lane & 8) ? E2[1] : E2[0], rE);
        }
        D2[0] = add2(D2[0], shfl_xor_u64(D2[0], 16));
        E2[0] = add2(E2[0], shfl_xor_u64(E2[0], 16));

        float ddA, ddB, ddC, ddD;
        unpack2(D2[0], ddA, ddB);
        unpack2(E2[0], ddC, ddD);
        ddA += cn_r;
        ddB += cn_r;
        ddC += cn_r;
        ddD += cn_r;

        // ---- softmax across the 16 slots, all four rows ----
        float mA = ddA, mB = ddB, mC = ddC, mD = ddD;
#pragma unroll
        for (int ofs = 1; ofs < 16; ofs <<= 1) {
            mA = fmaxf(mA, __shfl_xor_sync(0xffffffffu, mA, ofs));
            mB = fmaxf(mB, __shfl_xor_sync(0xffffffffu, mB, ofs));
            mC = fmaxf(mC, __shfl_xor_sync(0xffffffffu, mC, ofs));
            mD = fmaxf(mD, __shfl_xor_sync(0xffffffffu, mD, ofs));
        }
        const float eA = __expf(ddA - mA);
        const float eB = __expf(ddB - mB);
        const float eC = __expf(ddC - mC);
        const float eD = __expf(ddD - mD);
        float sA = eA, sB = eB, sC = eC, sD = eD;
#pragma unroll
        for (int ofs = 1; ofs < 16; ofs <<= 1) {
            sA += __shfl_xor_sync(0xffffffffu, sA, ofs);
            sB += __shfl_xor_sync(0xffffffffu, sB, ofs);
            sC += __shfl_xor_sync(0xffffffffu, sC, ofs);
            sD += __shfl_xor_sync(0xffffffffu, sD, ofs);
        }
        const float aA = __fdividef(eA, sA) + ATT_EPS;
        const float aB = __fdividef(eB, sB) + ATT_EPS;
        const float aC = __fdividef(eC, sC) + ATT_EPS;
        const float aD = __fdividef(eD, sD) + ATT_EPS;

        if (lane < 16) {
            g_attn[(size_t)r0 * NS + sigma] = aA;
            g_attn[(size_t)(r0 + 1) * NS + sigma] = aB;
            g_attn[(size_t)(r0 + 2) * NS + sigma] = aC;
            g_attn[(size_t)(r0 + 3) * NS + sigma] = aD;
        }
    }
}

// ---------------- K_accum: occ-1 full-row accumulators + 4-row unroll; S partials ----
__global__ void __launch_bounds__(256, 1)
k_accum() {
    __shared__ __align__(16) float ublk[NS * D];
    __shared__ float sblk[8][NS];

    const int tid = threadIdx.x;
    const int lane = tid & 31;
    const int warp = tid >> 5;

    ull u2[NS][4];
#pragma unroll
    for (int n = 0; n < NS; n++)
#pragma unroll
        for (int p = 0; p < 4; p++) u2[n][p] = 0ull;
    float s_acc[NS];
#pragma unroll
    for (int n = 0; n < NS; n++) s_acc[n] = 0.0f;

    const float4* x4 = reinterpret_cast<const float4*>(g_xln);
    const float4* ag4 = reinterpret_cast<const float4*>(g_attn);

    // 4 rows per pass (r0 multiple of 4; B_ROWS divisible by 4 -> r0+3 always valid)
    for (int r0 = (blockIdx.x * 8 + warp) * 4; r0 < B_ROWS; r0 += 4 * TOTW_ACC) {
        // ---- xln for all 4 rows upfront: 8 independent LDG.128 ----
        const float4 a0 = x4[(size_t)r0 * 64 + lane];
        const float4 a1 = x4[(size_t)r0 * 64 + 32 + lane];
        const float4 b0 = x4[(size_t)(r0 + 1) * 64 + lane];
        const float4 b1 = x4[(size_t)(r0 + 1) * 64 + 32 + lane];
        const float4 c0 = x4[(size_t)(r0 + 2) * 64 + lane];
        const float4 c1 = x4[(size_t)(r0 + 2) * 64 + 32 + lane];
        const float4 d0 = x4[(size_t)(r0 + 3) * 64 + lane];
        const float4 d1 = x4[(size_t)(r0 + 3) * 64 + 32 + lane];

        const ull xa0 = pack2(a0.x, a0.y), xa1 = pack2(a0.z, a0.w);
        const ull xa2 = pack2(a1.x, a1.y), xa3 = pack2(a1.z, a1.w);
        const ull xb0 = pack2(b0.x, b0.y), xb1 = pack2(b0.z, b0.w);
        const ull xb2 = pack2(b1.x, b1.y), xb3 = pack2(b1.z, b1.w);
        const ull xc0 = pack2(c0.x, c0.y), xc1 = pack2(c0.z, c0.w);
        const ull xc2 = pack2(c1.x, c1.y), xc3 = pack2(c1.z, c1.w);
        const ull xd0 = pack2(d0.x, d0.y), xd1 = pack2(d0.z, d0.w);
        const ull xd2 = pack2(d1.x, d1.y), xd3 = pack2(d1.z, d1.w);

        // ---- attn rows 0,1; FMA; then attn rows 2,3; FMA (bounds register pressure) ----
        {
            const float4 af0 = ag4[(size_t)r0 * 4 + 0];
            const float4 af1 = ag4[(size_t)r0 * 4 + 1];
            const float4 af2 = ag4[(size_t)r0 * 4 + 2];
            const float4 af3 = ag4[(size_t)r0 * 4 + 3];
            const float4 bf0 = ag4[(size_t)(r0 + 1) * 4 + 0];
            const float4 bf1 = ag4[(size_t)(r0 + 1) * 4 + 1];
            const float4 bf2 = ag4[(size_t)(r0 + 1) * 4 + 2];
            const float4 bf3 = ag4[(size_t)(r0 + 1) * 4 + 3];
            const float av[NS] = {af0.x, af0.y, af0.z, af0.w, af1.x, af1.y, af1.z, af1.w,
                                  af2.x, af2.y, af2.z, af2.w, af3.x, af3.y, af3.z, af3.w};
            const float bv[NS] = {bf0.x, bf0.y, bf0.z, bf0.w, bf1.x, bf1.y, bf1.z, bf1.w,
                                  bf2.x, bf2.y, bf2.z, bf2.w, bf3.x, bf3.y, bf3.z, bf3.w};
#pragma unroll
            for (int n = 0; n < NS; n++) {
                s_acc[n] += av[n] + bv[n];
                const ull a2 = pack2(av[n], av[n]);
                fma2(u2[n][0], a2, xa0);
                fma2(u2[n][1], a2, xa1);
                fma2(u2[n][2], a2, xa2);
                fma2(u2[n][3], a2, xa3);
                const ull b2v = pack2(bv[n], bv[n]);
                fma2(u2[n][0], b2v, xb0);
                fma2(u2[n][1], b2v, xb1);
                fma2(u2[n][2], b2v, xb2);
                fma2(u2[n][3], b2v, xb3);
            }
        }
        {
            const float4 cf0 = ag4[(size_t)(r0 + 2) * 4 + 0];
            const float4 cf1 = ag4[(size_t)(r0 + 2) * 4 + 1];
            const float4 cf2 = ag4[(size_t)(r0 + 2) * 4 + 2];
            const float4 cf3 = ag4[(size_t)(r0 + 2) * 4 + 3];
            const float4 df0 = ag4[(size_t)(r0 + 3) * 4 + 0];
            const float4 df1 = ag4[(size_t)(r0 + 3) * 4 + 1];
            const float4 df2 = ag4[(size_t)(r0 + 3) * 4 + 2];
            const float4 df3 = ag4[(size_t)(r0 + 3) * 4 + 3];
            const float cv[NS] = {cf0.x, cf0.y, cf0.z, cf0.w, cf1.x, cf1.y, cf1.z, cf1.w,
                                  cf2.x, cf2.y, cf2.z, cf2.w, cf3.x, cf3.y, cf3.z, cf3.w};
            const float dv[NS] = {df0.x, df0.y, df0.z, df0.w, df1.x, df1.y, df1.z, df1.w,
                                  df2.x, df2.y, df2.z, df2.w, df3.x, df3.y, df3.z, df3.w};
#pragma unroll
            for (int n = 0; n < NS; n++) {
                s_acc[n] += cv[n] + dv[n];
                const ull c2 = pack2(cv[n], cv[n]);
                fma2(u2[n][0], c2, xc0);
                fma2(u2[n][1], c2, xc1);
                fma2(u2[n][2], c2, xc2);
                fma2(u2[n][3], c2, xc3);
                const ull d2v = pack2(dv[n], dv[n]);
                fma2(u2[n][0], d2v, xd0);
                fma2(u2[n][1], d2v, xd1);
                fma2(u2[n][2], d2v, xd2);
                fma2(u2[n][3], d2v, xd3);
            }
        }
    }

    // stage per-warp partials into shared (serialized, deterministic)
    for (int w = 0; w < 8; w++) {
        if (warp == w) {
#pragma unroll
            for (int n = 0; n < NS; n++) {
#pragma unroll
                for (int p = 0; p < 4; p++) {
                    float lo, hi;
                    unpack2(u2[n][p], lo, hi);
                    const int c = (p < 2) ? (lane * 4 + 2 * p) : (128 + lane * 4 + 2 * (p - 2));
                    if (w == 0) {
                        ublk[n * D + c] = lo;
                        ublk[n * D + c + 1] = hi;
                    } else {
                        ublk[n * D + c] += lo;
                        ublk[n * D + c + 1] += hi;
                    }
                }
            }
            if (lane == 0) {
#pragma unroll
                for (int n = 0; n < NS; n++) sblk[w][n] = s_acc[n];
            }
        }
        __syncthreads();
    }

    for (int i = tid; i < NS * D; i += 256)
        g_partU[(size_t)blockIdx.x * (NS * D) + i] = ublk[i];
    if (tid < NS) {
        float t = 0.0f;
#pragma unroll
        for (int w = 0; w < 8; w++) t += sblk[w][tid];
        g_partS[blockIdx.x * NS + tid] = t;
    }
}

// ---------------- K_slot1: reduce partials + Wv -> updates (grid=NS, 1024 thr) ----------------
__global__ void __launch_bounds__(1024)
k_slot1(const float* __restrict__ Wv, const float* __restrict__ bv) {
    __shared__ __align__(16) float un_s[D];
    __shared__ float red[32];
    const int n = blockIdx.x, t = threadIdx.x;
    const int j = t >> 2, kq = t & 3;

    // U: 4 threads per column, 37 block-partials each
    {
        float a = 0.0f;
        const int base = kq * 37;
#pragma unroll
        for (int i = 0; i < 37; i++)
            a += g_partU[(size_t)(base + i) * (NS * D) + n * D + j];
        a += __shfl_xor_sync(0xffffffffu, a, 1);
        a += __shfl_xor_sync(0xffffffffu, a, 2);
        if (kq == 0) un_s[j] = a;
    }
    const float sv = (t < GRID_ACC) ? g_partS[t * NS + n] : 0.0f;
    const float S = block_sum1024(sv, red);  // internal syncs make un_s visible

    const float v = fc_dot(Wv, un_s, j, kq);
    if (kq == 0) g_updates[n * D + j] = v / S + bv[j];
}

// ---------------- K_gates: GRU gate GEMVs spread across chip (grid (NS,24)) ----------------
__global__ void __launch_bounds__(256)
k_gates(const float* __restrict__ W_ih, const float* __restrict__ W_hh,
        const float* __restrict__ b_ih, const float* __restrict__ b_hh) {
    __shared__ __align__(16) float in_s[D];
    const int n = blockIdx.x, y = blockIdx.y, tid = threadIdx.x;
    const bool is_x = (y < 12);
    const float* in = is_x ? (g_updates + n * D) : (g_slots + n * D);
    const float* W = is_x ? W_ih : W_hh;
    const float* bias = is_x ? b_ih : b_hh;
    float* out = is_x ? g_gx : g_gh;
    const int jbase = (is_x ? y : (y - 12)) * 64;

    in_s[tid] = in[tid];
    __syncthreads();

    const int j = jbase + (tid >> 2);
    const int kq = tid & 3;
    const float v = fc_dot(W, in_s, j, kq);
    if (kq == 0) out[n * 3 * D + j] = v + bias[j];
}

// ---------------- K_gru_ln: GRU combine + LN ----------------
__global__ void k_gru_ln(const float* __restrict__ gf, const float* __restrict__ bef) {
    __shared__ float red[32];
    const int n = blockIdx.x, t = threadIdx.x;
    const float xr = g_gx[n * 3 * D + t];
    const float xz = g_gx[n * 3 * D + D + t];
    const float xn = g_gx[n * 3 * D + 2 * D + t];
    const float hr = g_gh[n * 3 * D + t];
    const float hz = g_gh[n * 3 * D + D + t];
    const float hn = g_gh[n * 3 * D + 2 * D + t];
    const float h = g_slots[n * D + t];

    const float r = sigmoidf_(xr + hr);
    const float z = sigmoidf_(xz + hz);
    const float nn = tanhf(xn + r * hn);
    const float hnew = (1.0f - z) * nn + z * h;

    const float m = block_sum256(hnew, red) * (1.0f / (float)D);
    const float dv = hnew - m;
    const float var = block_sum256(dv * dv, red) * (1.0f / (float)D);
    const float lnf = dv * rsqrtf(var + LN_EPS) * gf[t] + bef[t];

    g_hnew[n * D + t] = hnew;
    g_lnf[n * D + t] = lnf;
}

// ---------------- K_ff1: hidden = relu(W1 @ lnf + b1) ----------------
__global__ void k_ff1(const float* __restrict__ W1, const float* __restrict__ b1) {
    __shared__ __align__(16) float in_s[D];
    const int n = blockIdx.x, tid = threadIdx.x;
    in_s[tid] = g_lnf[n * D + tid];
    __syncthreads();
    const int j = blockIdx.y * 64 + (tid >> 2);
    const int kq = tid & 3;
    const float v = fc_dot(W1, in_s, j, kq);
    if (kq == 0) g_hd[n * D + j] = fmaxf(v + b1[j], 0.0f);
}

// ---------------- K_ff2: res = hnew + W2 @ hidden + b2 -> slots (+out) ----------------
__global__ void k_ff2(const float* __restrict__ W2, const float* __restrict__ b2,
                      float* __restrict__ out, int write_out) {
    __shared__ __align__(16) float in_s[D];
    const int n = blockIdx.x, tid = threadIdx.x;
    in_s[tid] = g_hd[n * D + tid];
    __syncthreads();
    const int j = blockIdx.y * 64 + (tid >> 2);
    const int kq = tid & 3;
    const float v = fc_dot(W2, in_s, j, kq);
    if (kq == 0) {
        const float res = g_hnew[n * D + j] + v + b2[j];
        g_slots[n * D + j] = res;
        if (write_out) out[n * D + j] = res;
    }
}

// ---------------- K_prep: LN(slots) -> q -> qk, cn (grid=NS, 1024 thr) ----------------
__global__ void __launch_bounds__(1024)
k_prep(const float* __restrict__ Wq, const float* __restrict__ bq,
       const float* __restrict__ bk,
       const float* __restrict__ gs, const float* __restrict__ bes) {
    __shared__ __align__(16) float h_s[D];
    __shared__ __align__(16) float s_s[D];
    __shared__ __align__(16) float q_s[D];
    __shared__ float red[32];
    const int n = blockIdx.x, t = threadIdx.x;

    if (t < D) h_s[t] = g_slots[n * D + t];
    __syncthreads();
    ln256_1024(h_s, s_s, gs, bes, red);
    q_qk_1024(n, s_s, q_s, Wq, bq, bk, red);
}

// ---------------- launch ----------------
extern "C" void kernel_launch(void* const* d_in, const int* in_sizes, int n_in,
                              void* d_out, int out_size) {
    const float* x      = (const float*)d_in[0];
    const float* noise  = (const float*)d_in[1];
    const float* mu     = (const float*)d_in[2];
    const float* sigma  = (const float*)d_in[3];
    const float* Wq     = (const float*)d_in[4];
    const float* bq     = (const float*)d_in[5];
    const float* Wk     = (const float*)d_in[6];
    const float* bk     = (const float*)d_in[7];
    const float* Wv     = (const float*)d_in[8];
    const float* bv     = (const float*)d_in[9];
    const float* W_ih   = (const float*)d_in[10];
    const float* W_hh   = (const float*)d_in[11];
    const float* b_ih   = (const float*)d_in[12];
    const float* b_hh   = (const float*)d_in[13];
    const float* W1     = (const float*)d_in[14];
    const float* b1     = (const float*)d_in[15];
    const float* W2     = (const float*)d_in[16];
    const float* b2     = (const float*)d_in[17];
    const float* g_in   = (const float*)d_in[18];
    const float* be_in  = (const float*)d_in[19];
    const float* g_s    = (const float*)d_in[20];
    const float* be_s   = (const float*)d_in[21];
    const float* g_f    = (const float*)d_in[22];
    const float* be_f   = (const float*)d_in[23];
    float* out = (float*)d_out;

    k_lnx<<<1024, 256>>>(x, g_in, be_in);
    k_wkT<<<dim3(8, 8), dim3(32, 8)>>>(Wk);
    k_init<<<NS, 1024>>>(noise, mu, sigma, Wq, bq, bk, g_s, be_s);

    for (int it = 0; it < 3; it++) {
        k_dots<<<GRID_DOTS, 256>>>();
        k_accum<<<GRID_ACC, 256>>>();
        k_slot1<<<NS, 1024>>>(Wv, bv);
        k_gates<<<dim3(NS, 24), 256>>>(W_ih, W_hh, b_ih, b_hh);
        k_gru_ln<<<NS, D>>>(g_f, be_f);
        k_ff1<<<dim3(NS, 4), 256>>>(W1, b1);
        k_ff2<<<dim3(NS, 4), 256>>>(W2, b2, out, it == 2 ? 1 : 0);
        if (it < 2) k_prep<<<NS, 1024>>>(Wq, bq, bk, g_s, be_s);
    }
}